// round 3
// baseline (speedup 1.0000x reference)
#include <cuda_runtime.h>
#include <cstdint>
#include <math.h>

// Problem constants (fixed by the reference setup_inputs)
#define T_TOK   1024
#define H_DIM   1024
#define I_DIM   2816
#define E_NUM   8
#define S_NUM   (T_TOK * 2)      // 2048 (token, expert) slots
#define MAX_TILES 24             // worst-case sum of ceil(n_e/128) over experts

// GEMM tiling
#define BM 128
#define BN 64
#define BK 32
#define LDSK 36                  // BK + 4 pad (conflict-free fragment loads)

// ---------------- device scratch (static, allocation-free) ----------------
__device__ int   d_slot_token[S_NUM];
__device__ float d_slot_gate[S_NUM];
__device__ int   d_tile_e[MAX_TILES];
__device__ int   d_tile_r0[MAX_TILES];
__device__ int   d_tile_r1[MAX_TILES];
__device__ int   d_num_tiles;
__device__ __align__(16) float d_act[(size_t)S_NUM * I_DIM];   // ~23 MB

// ---------------- helpers ----------------
__device__ __forceinline__ unsigned tf32u(float x) {
    unsigned u;
    asm("cvt.rna.tf32.f32 %0, %1;" : "=r"(u) : "f"(x));
    return u;
}

__device__ __forceinline__ void mma_tf32(float c[4], const unsigned a[4], const unsigned b[2]) {
    asm volatile(
        "mma.sync.aligned.m16n8k8.row.col.f32.tf32.tf32.f32 "
        "{%0,%1,%2,%3}, {%4,%5,%6,%7}, {%8,%9}, {%0,%1,%2,%3};\n"
        : "+f"(c[0]), "+f"(c[1]), "+f"(c[2]), "+f"(c[3])
        : "r"(a[0]), "r"(a[1]), "r"(a[2]), "r"(a[3]),
          "r"(b[0]), "r"(b[1]));
}

// ---------------- zero output ----------------
__global__ void zero_kernel(float* __restrict__ out) {
    out[blockIdx.x * blockDim.x + threadIdx.x] = 0.0f;
}

// ---------------- router: top-2 softmax gates + expert-grouped slots ----------------
__global__ void router_kernel(const float* __restrict__ logits) {
    __shared__ int s_cnt[E_NUM];
    __shared__ int s_off[E_NUM + 1];
    __shared__ int s_cur[E_NUM];

    int t = threadIdx.x;            // one token per thread, blockDim == T_TOK
    if (t < E_NUM) s_cnt[t] = 0;
    __syncthreads();

    float l[E_NUM];
#pragma unroll
    for (int e = 0; e < E_NUM; e++) l[e] = logits[t * E_NUM + e];

    int e0 = 0;
#pragma unroll
    for (int e = 1; e < E_NUM; e++) if (l[e] > l[e0]) e0 = e;
    int e1 = (e0 == 0) ? 1 : 0;
#pragma unroll
    for (int e = 0; e < E_NUM; e++) if (e != e0 && l[e] > l[e1]) e1 = e;

    // renormalized top-2 softmax == softmax over {l0, l1}
    float d  = expf(l[e1] - l[e0]);       // <= 1
    float g0 = 1.0f / (1.0f + d);
    float g1 = 1.0f - g0;

    atomicAdd(&s_cnt[e0], 1);
    atomicAdd(&s_cnt[e1], 1);
    __syncthreads();

    if (t == 0) {
        int acc = 0;
        for (int e = 0; e < E_NUM; e++) { s_off[e] = acc; s_cur[e] = acc; acc += s_cnt[e]; }
        s_off[E_NUM] = acc;   // == S_NUM
    }
    __syncthreads();

    int p0 = atomicAdd(&s_cur[e0], 1);
    d_slot_token[p0] = t; d_slot_gate[p0] = g0;
    int p1 = atomicAdd(&s_cur[e1], 1);
    d_slot_token[p1] = t; d_slot_gate[p1] = g1;

    if (t == 0) {
        int nt = 0;
        for (int e = 0; e < E_NUM; e++) {
            for (int r = s_off[e]; r < s_off[e + 1]; r += BM) {
                d_tile_e[nt]  = e;
                d_tile_r0[nt] = r;
                d_tile_r1[nt] = min(r + BM, s_off[e + 1]);
                nt++;
            }
        }
        d_num_tiles = nt;
    }
}

// ---------------- GEMM1: act[slot, I] = silu(X@W1^T) * (X@W3^T)  ----------------
// grid: (I_DIM/BN, MAX_TILES), block: 256
__global__ __launch_bounds__(256)
void gemm1_kernel(const float* __restrict__ X,
                  const float* __restrict__ W1,
                  const float* __restrict__ W3) {
    int tile = blockIdx.y;
    if (tile >= d_num_tiles) return;
    const int e    = d_tile_e[tile];
    const int r0   = d_tile_r0[tile];
    const int rows = d_tile_r1[tile] - r0;
    const int n0   = blockIdx.x * BN;

    __shared__ float sA[BM * LDSK];
    __shared__ float sB1[BN * LDSK];
    __shared__ float sB3[BN * LDSK];

    const int tid  = threadIdx.x;
    const int warp = tid >> 5, lane = tid & 31;
    const int g = lane >> 2, tg = lane & 3;
    const int wm = warp & 3, wn = warp >> 2;   // warp tile origin (wm*32, wn*32)

    const int lrow = tid >> 3;       // 0..31
    const int lk   = (tid & 7) * 4;  // 0..28 step 4

    int tok[4];
#pragma unroll
    for (int i = 0; i < 4; i++) {
        int r = lrow + 32 * i;
        tok[i] = (r < rows) ? d_slot_token[r0 + r] : -1;
    }

    const float* W1e = W1 + (size_t)e * I_DIM * H_DIM;
    const float* W3e = W3 + (size_t)e * I_DIM * H_DIM;

    float acc1[2][4][4], acc3[2][4][4];
#pragma unroll
    for (int a = 0; a < 2; a++)
#pragma unroll
        for (int b = 0; b < 4; b++)
#pragma unroll
            for (int c = 0; c < 4; c++) { acc1[a][b][c] = 0.f; acc3[a][b][c] = 0.f; }

    for (int kt = 0; kt < H_DIM; kt += BK) {
        // load A (gathered token rows), converted to tf32
#pragma unroll
        for (int i = 0; i < 4; i++) {
            int r = lrow + 32 * i;
            float4 v = make_float4(0.f, 0.f, 0.f, 0.f);
            if (tok[i] >= 0)
                v = *(const float4*)(X + (size_t)tok[i] * H_DIM + kt + lk);
            float* dst = &sA[r * LDSK + lk];
            dst[0] = __uint_as_float(tf32u(v.x));
            dst[1] = __uint_as_float(tf32u(v.y));
            dst[2] = __uint_as_float(tf32u(v.z));
            dst[3] = __uint_as_float(tf32u(v.w));
        }
        // load B1/B3 tiles [n][k]
#pragma unroll
        for (int i = 0; i < 2; i++) {
            int r = lrow + 32 * i;   // 0..63
            float4 v1 = *(const float4*)(W1e + (size_t)(n0 + r) * H_DIM + kt + lk);
            float4 v3 = *(const float4*)(W3e + (size_t)(n0 + r) * H_DIM + kt + lk);
            float* d1 = &sB1[r * LDSK + lk];
            d1[0] = __uint_as_float(tf32u(v1.x));
            d1[1] = __uint_as_float(tf32u(v1.y));
            d1[2] = __uint_as_float(tf32u(v1.z));
            d1[3] = __uint_as_float(tf32u(v1.w));
            float* d3 = &sB3[r * LDSK + lk];
            d3[0] = __uint_as_float(tf32u(v3.x));
            d3[1] = __uint_as_float(tf32u(v3.y));
            d3[2] = __uint_as_float(tf32u(v3.z));
            d3[3] = __uint_as_float(tf32u(v3.w));
        }
        __syncthreads();

#pragma unroll
        for (int ks = 0; ks < BK; ks += 8) {
            unsigned a[2][4], b1[4][2], b3[4][2];
#pragma unroll
            for (int mt = 0; mt < 2; mt++) {
                int mb = wm * 32 + mt * 16;
                a[mt][0] = __float_as_uint(sA[(mb + g)     * LDSK + ks + tg]);
                a[mt][1] = __float_as_uint(sA[(mb + g + 8) * LDSK + ks + tg]);
                a[mt][2] = __float_as_uint(sA[(mb + g)     * LDSK + ks + tg + 4]);
                a[mt][3] = __float_as_uint(sA[(mb + g + 8) * LDSK + ks + tg + 4]);
            }
#pragma unroll
            for (int nt = 0; nt < 4; nt++) {
                int nb = wn * 32 + nt * 8;
                b1[nt][0] = __float_as_uint(sB1[(nb + g) * LDSK + ks + tg]);
                b1[nt][1] = __float_as_uint(sB1[(nb + g) * LDSK + ks + tg + 4]);
                b3[nt][0] = __float_as_uint(sB3[(nb + g) * LDSK + ks + tg]);
                b3[nt][1] = __float_as_uint(sB3[(nb + g) * LDSK + ks + tg + 4]);
            }
#pragma unroll
            for (int mt = 0; mt < 2; mt++)
#pragma unroll
                for (int nt = 0; nt < 4; nt++) {
                    mma_tf32(acc1[mt][nt], a[mt], b1[nt]);
                    mma_tf32(acc3[mt][nt], a[mt], b3[nt]);
                }
        }
        __syncthreads();
    }

    // epilogue: act = silu(h1) * h3
#pragma unroll
    for (int mt = 0; mt < 2; mt++) {
#pragma unroll
        for (int nt = 0; nt < 4; nt++) {
#pragma unroll
            for (int i = 0; i < 4; i++) {
                int m = wm * 32 + mt * 16 + g + ((i >= 2) ? 8 : 0);
                int n = wn * 32 + nt * 8 + tg * 2 + (i & 1);
                if (m < rows) {
                    float h1 = acc1[mt][nt][i];
                    float h3 = acc3[mt][nt][i];
                    float act = (h1 / (1.0f + __expf(-h1))) * h3;
                    d_act[(size_t)(r0 + m) * I_DIM + n0 + n] = act;
                }
            }
        }
    }
}

// ---------------- GEMM2: out[token, H] += gate * (act @ W2^T) ----------------
// grid: (H_DIM/BN, MAX_TILES), block: 256
__global__ __launch_bounds__(256)
void gemm2_kernel(const float* __restrict__ W2, float* __restrict__ out) {
    int tile = blockIdx.y;
    if (tile >= d_num_tiles) return;
    const int e    = d_tile_e[tile];
    const int r0   = d_tile_r0[tile];
    const int rows = d_tile_r1[tile] - r0;
    const int n0   = blockIdx.x * BN;

    __shared__ float sA[BM * LDSK];
    __shared__ float sB[BN * LDSK];

    const int tid  = threadIdx.x;
    const int warp = tid >> 5, lane = tid & 31;
    const int g = lane >> 2, tg = lane & 3;
    const int wm = warp & 3, wn = warp >> 2;

    const int lrow = tid >> 3;
    const int lk   = (tid & 7) * 4;

    const float* W2e = W2 + (size_t)e * H_DIM * I_DIM;

    float acc[2][4][4];
#pragma unroll
    for (int a = 0; a < 2; a++)
#pragma unroll
        for (int b = 0; b < 4; b++)
#pragma unroll
            for (int c = 0; c < 4; c++) acc[a][b][c] = 0.f;

    for (int kt = 0; kt < I_DIM; kt += BK) {
#pragma unroll
        for (int i = 0; i < 4; i++) {
            int r = lrow + 32 * i;
            float4 v = make_float4(0.f, 0.f, 0.f, 0.f);
            if (r < rows)
                v = *(const float4*)(d_act + (size_t)(r0 + r) * I_DIM + kt + lk);
            float* dst = &sA[r * LDSK + lk];
            dst[0] = __uint_as_float(tf32u(v.x));
            dst[1] = __uint_as_float(tf32u(v.y));
            dst[2] = __uint_as_float(tf32u(v.z));
            dst[3] = __uint_as_float(tf32u(v.w));
        }
#pragma unroll
        for (int i = 0; i < 2; i++) {
            int r = lrow + 32 * i;
            float4 v = *(const float4*)(W2e + (size_t)(n0 + r) * I_DIM + kt + lk);
            float* db = &sB[r * LDSK + lk];
            db[0] = __uint_as_float(tf32u(v.x));
            db[1] = __uint_as_float(tf32u(v.y));
            db[2] = __uint_as_float(tf32u(v.z));
            db[3] = __uint_as_float(tf32u(v.w));
        }
        __syncthreads();

#pragma unroll
        for (int ks = 0; ks < BK; ks += 8) {
            unsigned a[2][4], b[4][2];
#pragma unroll
            for (int mt = 0; mt < 2; mt++) {
                int mb = wm * 32 + mt * 16;
                a[mt][0] = __float_as_uint(sA[(mb + g)     * LDSK + ks + tg]);
                a[mt][1] = __float_as_uint(sA[(mb + g + 8) * LDSK + ks + tg]);
                a[mt][2] = __float_as_uint(sA[(mb + g)     * LDSK + ks + tg + 4]);
                a[mt][3] = __float_as_uint(sA[(mb + g + 8) * LDSK + ks + tg + 4]);
            }
#pragma unroll
            for (int nt = 0; nt < 4; nt++) {
                int nb = wn * 32 + nt * 8;
                b[nt][0] = __float_as_uint(sB[(nb + g) * LDSK + ks + tg]);
                b[nt][1] = __float_as_uint(sB[(nb + g) * LDSK + ks + tg + 4]);
            }
#pragma unroll
            for (int mt = 0; mt < 2; mt++)
#pragma unroll
                for (int nt = 0; nt < 4; nt++)
                    mma_tf32(acc[mt][nt], a[mt], b[nt]);
        }
        __syncthreads();
    }

    // epilogue: weighted scatter-add into out. Exactly 2 contributions per
    // (token, h) location; fp32 add is commutative, so the result is
    // bitwise deterministic regardless of atomic ordering.
    int   tok_h[2][2];
    float gat_h[2][2];
#pragma unroll
    for (int mt = 0; mt < 2; mt++)
#pragma unroll
        for (int hh = 0; hh < 2; hh++) {
            int m = wm * 32 + mt * 16 + g + hh * 8;
            if (m < rows) {
                tok_h[mt][hh] = d_slot_token[r0 + m];
                gat_h[mt][hh] = d_slot_gate[r0 + m];
            } else {
                tok_h[mt][hh] = -1;
                gat_h[mt][hh] = 0.f;
            }
        }

#pragma unroll
    for (int mt = 0; mt < 2; mt++) {
#pragma unroll
        for (int nt = 0; nt < 4; nt++) {
#pragma unroll
            for (int i = 0; i < 4; i++) {
                int hh = (i >= 2) ? 1 : 0;
                int tok = tok_h[mt][hh];
                if (tok >= 0) {
                    int n = n0 + wn * 32 + nt * 8 + tg * 2 + (i & 1);
                    atomicAdd(&out[(size_t)tok * H_DIM + n],
                              gat_h[mt][hh] * acc[mt][nt][i]);
                }
            }
        }
    }
}

// ---------------- launch ----------------
extern "C" void kernel_launch(void* const* d_in, const int* in_sizes, int n_in,
                              void* d_out, int out_size) {
    const float* hs     = (const float*)d_in[0];   // [T, H]
    const float* logits = (const float*)d_in[1];   // [T, E]
    const float* w1     = (const float*)d_in[2];   // [E, I, H]
    const float* w3     = (const float*)d_in[3];   // [E, I, H]
    const float* w2     = (const float*)d_in[4];   // [E, H, I]
    float* out = (float*)d_out;                    // [T, H]

    zero_kernel<<<(T_TOK * H_DIM) / 256, 256>>>(out);
    router_kernel<<<1, T_TOK>>>(logits);
    gemm1_kernel<<<dim3(I_DIM / BN, MAX_TILES), 256>>>(hs, w1, w3);
    gemm2_kernel<<<dim3(H_DIM / BN, MAX_TILES), 256>>>(w2, out);
}

// round 5
// speedup vs baseline: 1.4915x; 1.4915x over previous
#include <cuda_runtime.h>
#include <cuda_fp16.h>
#include <cstdint>
#include <math.h>

// Problem constants (fixed by the reference setup_inputs)
#define T_TOK   1024
#define H_DIM   1024
#define I_DIM   2816
#define E_NUM   8
#define S_NUM   (T_TOK * 2)      // 2048 (token, expert) slots
#define MAX_TILES 24

// GEMM tiling
#define BM 128
#define BN 64
#define BK 32
#define LDA 40                   // 32 + 8 halfs pad: 80B row stride -> conflict-free LDSM

// ---------------- device scratch (static, allocation-free) ----------------
__device__ int   d_slot_token[S_NUM];
__device__ float d_slot_gate[S_NUM];
__device__ int   d_tile_e[MAX_TILES];
__device__ int   d_tile_r0[MAX_TILES];
__device__ int   d_tile_r1[MAX_TILES];
__device__ int   d_num_tiles;
__device__ __align__(16) __half d_act[(size_t)S_NUM * I_DIM];   // 11.5 MB fp16

// ---------------- helpers ----------------
__device__ __forceinline__ uint32_t smem_u32(const void* p) {
    return (uint32_t)__cvta_generic_to_shared(p);
}

__device__ __forceinline__ void ldsm_x4(uint32_t* r, uint32_t addr) {
    asm volatile("ldmatrix.sync.aligned.m8n8.x4.shared.b16 {%0,%1,%2,%3}, [%4];"
                 : "=r"(r[0]), "=r"(r[1]), "=r"(r[2]), "=r"(r[3]) : "r"(addr));
}

__device__ __forceinline__ void mma_f16(float c[4], const uint32_t a[4], uint32_t b0, uint32_t b1) {
    asm volatile(
        "mma.sync.aligned.m16n8k16.row.col.f32.f16.f16.f32 "
        "{%0,%1,%2,%3}, {%4,%5,%6,%7}, {%8,%9}, {%0,%1,%2,%3};\n"
        : "+f"(c[0]), "+f"(c[1]), "+f"(c[2]), "+f"(c[3])
        : "r"(a[0]), "r"(a[1]), "r"(a[2]), "r"(a[3]), "r"(b0), "r"(b1));
}

__device__ __forceinline__ uint32_t pack2(float x, float y) {
    __half2 h = __floats2half2_rn(x, y);
    return *reinterpret_cast<uint32_t*>(&h);
}

// ---------------- zero output ----------------
__global__ void zero_kernel(float* __restrict__ out) {
    out[blockIdx.x * blockDim.x + threadIdx.x] = 0.0f;
}

// ---------------- router: top-2 softmax gates + expert-grouped slots ----------------
__global__ void router_kernel(const float* __restrict__ logits) {
    __shared__ int s_cnt[E_NUM];
    __shared__ int s_off[E_NUM + 1];
    __shared__ int s_cur[E_NUM];

    int t = threadIdx.x;            // one token per thread, blockDim == T_TOK
    if (t < E_NUM) s_cnt[t] = 0;
    __syncthreads();

    float l[E_NUM];
#pragma unroll
    for (int e = 0; e < E_NUM; e++) l[e] = logits[t * E_NUM + e];

    int e0 = 0;
#pragma unroll
    for (int e = 1; e < E_NUM; e++) if (l[e] > l[e0]) e0 = e;
    int e1 = (e0 == 0) ? 1 : 0;
#pragma unroll
    for (int e = 0; e < E_NUM; e++) if (e != e0 && l[e] > l[e1]) e1 = e;

    // renormalized top-2 softmax == softmax over {l0, l1}
    float d  = expf(l[e1] - l[e0]);       // <= 1
    float g0 = 1.0f / (1.0f + d);
    float g1 = 1.0f - g0;

    atomicAdd(&s_cnt[e0], 1);
    atomicAdd(&s_cnt[e1], 1);
    __syncthreads();

    if (t == 0) {
        int acc = 0;
        for (int e = 0; e < E_NUM; e++) { s_off[e] = acc; s_cur[e] = acc; acc += s_cnt[e]; }
        s_off[E_NUM] = acc;   // == S_NUM
    }
    __syncthreads();

    int p0 = atomicAdd(&s_cur[e0], 1);
    d_slot_token[p0] = t; d_slot_gate[p0] = g0;
    int p1 = atomicAdd(&s_cur[e1], 1);
    d_slot_token[p1] = t; d_slot_gate[p1] = g1;

    if (t == 0) {
        int nt = 0;
        for (int e = 0; e < E_NUM; e++) {
            for (int r = s_off[e]; r < s_off[e + 1]; r += BM) {
                d_tile_e[nt]  = e;
                d_tile_r0[nt] = r;
                d_tile_r1[nt] = min(r + BM, s_off[e + 1]);
                nt++;
            }
        }
        d_num_tiles = nt;
    }
}

// ---------------- GEMM1: act[slot, I] = silu(X@W1^T) * (X@W3^T), fp16 MMA ----------------
// grid: (I_DIM/BN, MAX_TILES), block: 256 (8 warps: 4 x 2)
__global__ __launch_bounds__(256, 1)
void gemm1_kernel(const float* __restrict__ X,
                  const float* __restrict__ W1,
                  const float* __restrict__ W3) {
    int tile = blockIdx.y;
    if (tile >= d_num_tiles) return;
    const int e    = d_tile_e[tile];
    const int r0   = d_tile_r0[tile];
    const int rows = d_tile_r1[tile] - r0;
    const int n0   = blockIdx.x * BN;

    __shared__ __half sA [BM * LDA];
    __shared__ __half sB1[BN * LDA];
    __shared__ __half sB3[BN * LDA];

    const int tid  = threadIdx.x;
    const int warp = tid >> 5, lane = tid & 31;
    const int g = lane >> 2, tg = lane & 3;
    const int wm = warp & 3, wn = warp >> 2;     // warp tile (wm*32, wn*32)
    const int lrow = tid >> 3;                   // 0..31
    const int lk   = (tid & 7) * 4;              // 0..28 step 4
    const int q = lane >> 3, j = lane & 7;       // ldmatrix lane decomposition

    int tok[4];
#pragma unroll
    for (int i = 0; i < 4; i++) {
        int r = lrow + 32 * i;
        tok[i] = (r < rows) ? d_slot_token[r0 + r] : -1;
    }

    const float* W1e = W1 + (size_t)e * I_DIM * H_DIM;
    const float* W3e = W3 + (size_t)e * I_DIM * H_DIM;

    // register staging (double buffer vs smem)
    float4 rA[4], rB1[2], rB3[2];
#pragma unroll
    for (int i = 0; i < 4; i++)
        rA[i] = (tok[i] >= 0) ? *(const float4*)(X + (size_t)tok[i] * H_DIM + lk)
                              : make_float4(0.f, 0.f, 0.f, 0.f);
#pragma unroll
    for (int i = 0; i < 2; i++) {
        rB1[i] = *(const float4*)(W1e + (size_t)(n0 + lrow + 32 * i) * H_DIM + lk);
        rB3[i] = *(const float4*)(W3e + (size_t)(n0 + lrow + 32 * i) * H_DIM + lk);
    }

    float acc1[2][4][4], acc3[2][4][4];
#pragma unroll
    for (int a = 0; a < 2; a++)
#pragma unroll
        for (int b = 0; b < 4; b++)
#pragma unroll
            for (int c = 0; c < 4; c++) { acc1[a][b][c] = 0.f; acc3[a][b][c] = 0.f; }

    for (int kt = 0; kt < H_DIM; kt += BK) {
        // commit staged regs to smem (fp32 -> fp16)
#pragma unroll
        for (int i = 0; i < 4; i++) {
            uint2 u;
            u.x = pack2(rA[i].x, rA[i].y);
            u.y = pack2(rA[i].z, rA[i].w);
            *(uint2*)&sA[(lrow + 32 * i) * LDA + lk] = u;
        }
#pragma unroll
        for (int i = 0; i < 2; i++) {
            uint2 u1, u3;
            u1.x = pack2(rB1[i].x, rB1[i].y); u1.y = pack2(rB1[i].z, rB1[i].w);
            u3.x = pack2(rB3[i].x, rB3[i].y); u3.y = pack2(rB3[i].z, rB3[i].w);
            *(uint2*)&sB1[(lrow + 32 * i) * LDA + lk] = u1;
            *(uint2*)&sB3[(lrow + 32 * i) * LDA + lk] = u3;
        }
        __syncthreads();

        // prefetch next K tile into registers
        if (kt + BK < H_DIM) {
            int kn = kt + BK;
#pragma unroll
            for (int i = 0; i < 4; i++)
                rA[i] = (tok[i] >= 0) ? *(const float4*)(X + (size_t)tok[i] * H_DIM + kn + lk)
                                      : make_float4(0.f, 0.f, 0.f, 0.f);
#pragma unroll
            for (int i = 0; i < 2; i++) {
                rB1[i] = *(const float4*)(W1e + (size_t)(n0 + lrow + 32 * i) * H_DIM + kn + lk);
                rB3[i] = *(const float4*)(W3e + (size_t)(n0 + lrow + 32 * i) * H_DIM + kn + lk);
            }
        }

        // compute: 2 k-steps of m16n8k16
#pragma unroll
        for (int ks = 0; ks < BK; ks += 16) {
            uint32_t af[2][4];
#pragma unroll
            for (int mt = 0; mt < 2; mt++) {
                int arow = wm * 32 + mt * 16 + j + (q & 1) * 8;
                int acol = ks + (q >> 1) * 8;
                ldsm_x4(af[mt], smem_u32(&sA[arow * LDA + acol]));
            }
            uint32_t bf1[2][4], bf3[2][4];
#pragma unroll
            for (int pr = 0; pr < 2; pr++) {
                int brow = wn * 32 + pr * 16 + j + (q >> 1) * 8;
                int bcol = ks + (q & 1) * 8;
                uint32_t addr1 = smem_u32(&sB1[brow * LDA + bcol]);
                uint32_t addr3 = smem_u32(&sB3[brow * LDA + bcol]);
                ldsm_x4(bf1[pr], addr1);
                ldsm_x4(bf3[pr], addr3);
            }
#pragma unroll
            for (int mt = 0; mt < 2; mt++)
#pragma unroll
                for (int nt = 0; nt < 4; nt++) {
                    int pr = nt >> 1, o = (nt & 1) * 2;
                    mma_f16(acc1[mt][nt], af[mt], bf1[pr][o], bf1[pr][o + 1]);
                    mma_f16(acc3[mt][nt], af[mt], bf3[pr][o], bf3[pr][o + 1]);
                }
        }
        __syncthreads();
    }

    // epilogue: act = silu(h1) * h3, stored fp16 as half2
#pragma unroll
    for (int mt = 0; mt < 2; mt++) {
#pragma unroll
        for (int nt = 0; nt < 4; nt++) {
#pragma unroll
            for (int p = 0; p < 2; p++) {
                int m = wm * 32 + mt * 16 + g + p * 8;
                if (m < rows) {
                    float h1a = acc1[mt][nt][2 * p],     h3a = acc3[mt][nt][2 * p];
                    float h1b = acc1[mt][nt][2 * p + 1], h3b = acc3[mt][nt][2 * p + 1];
                    float va = (h1a / (1.0f + __expf(-h1a))) * h3a;
                    float vb = (h1b / (1.0f + __expf(-h1b))) * h3b;
                    int n = n0 + wn * 32 + nt * 8 + tg * 2;
                    *(__half2*)&d_act[(size_t)(r0 + m) * I_DIM + n] =
                        __floats2half2_rn(va, vb);
                }
            }
        }
    }
}

// ---------------- GEMM2: out[token, H] += gate * (act @ W2^T), fp16 MMA ----------------
// grid: (H_DIM/BN, MAX_TILES), block: 256
__global__ __launch_bounds__(256, 1)
void gemm2_kernel(const float* __restrict__ W2, float* __restrict__ out) {
    int tile = blockIdx.y;
    if (tile >= d_num_tiles) return;
    const int e    = d_tile_e[tile];
    const int r0   = d_tile_r0[tile];
    const int rows = d_tile_r1[tile] - r0;
    const int n0   = blockIdx.x * BN;

    __shared__ __half sA[BM * LDA];
    __shared__ __half sB[BN * LDA];

    const int tid  = threadIdx.x;
    const int warp = tid >> 5, lane = tid & 31;
    const int g = lane >> 2, tg = lane & 3;
    const int wm = warp & 3, wn = warp >> 2;
    const int lrow = tid >> 3;
    const int lk   = (tid & 7) * 4;
    const int q = lane >> 3, j = lane & 7;

    const float* W2e = W2 + (size_t)e * H_DIM * I_DIM;

    bool arow_ok[4];
#pragma unroll
    for (int i = 0; i < 4; i++) arow_ok[i] = (lrow + 32 * i) < rows;

    uint2  rA[4];         // fp16 source: 4 halfs per load
    float4 rB[2];
#pragma unroll
    for (int i = 0; i < 4; i++)
        rA[i] = arow_ok[i] ? *(const uint2*)(d_act + (size_t)(r0 + lrow + 32 * i) * I_DIM + lk)
                           : make_uint2(0u, 0u);
#pragma unroll
    for (int i = 0; i < 2; i++)
        rB[i] = *(const float4*)(W2e + (size_t)(n0 + lrow + 32 * i) * I_DIM + lk);

    float acc[2][4][4];
#pragma unroll
    for (int a = 0; a < 2; a++)
#pragma unroll
        for (int b = 0; b < 4; b++)
#pragma unroll
            for (int c = 0; c < 4; c++) acc[a][b][c] = 0.f;

    for (int kt = 0; kt < I_DIM; kt += BK) {
#pragma unroll
        for (int i = 0; i < 4; i++)
            *(uint2*)&sA[(lrow + 32 * i) * LDA + lk] = rA[i];
#pragma unroll
        for (int i = 0; i < 2; i++) {
            uint2 u;
            u.x = pack2(rB[i].x, rB[i].y);
            u.y = pack2(rB[i].z, rB[i].w);
            *(uint2*)&sB[(lrow + 32 * i) * LDA + lk] = u;
        }
        __syncthreads();

        if (kt + BK < I_DIM) {
            int kn = kt + BK;
#pragma unroll
            for (int i = 0; i < 4; i++)
                rA[i] = arow_ok[i]
                      ? *(const uint2*)(d_act + (size_t)(r0 + lrow + 32 * i) * I_DIM + kn + lk)
                      : make_uint2(0u, 0u);
#pragma unroll
            for (int i = 0; i < 2; i++)
                rB[i] = *(const float4*)(W2e + (size_t)(n0 + lrow + 32 * i) * I_DIM + kn + lk);
        }

#pragma unroll
        for (int ks = 0; ks < BK; ks += 16) {
            uint32_t af[2][4];
#pragma unroll
            for (int mt = 0; mt < 2; mt++) {
                int arow = wm * 32 + mt * 16 + j + (q & 1) * 8;
                int acol = ks + (q >> 1) * 8;
                ldsm_x4(af[mt], smem_u32(&sA[arow * LDA + acol]));
            }
            uint32_t bf[2][4];
#pragma unroll
            for (int pr = 0; pr < 2; pr++) {
                int brow = wn * 32 + pr * 16 + j + (q >> 1) * 8;
                int bcol = ks + (q & 1) * 8;
                ldsm_x4(bf[pr], smem_u32(&sB[brow * LDA + bcol]));
            }
#pragma unroll
            for (int mt = 0; mt < 2; mt++)
#pragma unroll
                for (int nt = 0; nt < 4; nt++) {
                    int pr = nt >> 1, o = (nt & 1) * 2;
                    mma_f16(acc[mt][nt], af[mt], bf[pr][o], bf[pr][o + 1]);
                }
        }
        __syncthreads();
    }

    // epilogue: weighted scatter-add (exactly 2 contributions per (token, h);
    // fp32 add is commutative -> bitwise deterministic)
    int   tok_h[2][2];
    float gat_h[2][2];
#pragma unroll
    for (int mt = 0; mt < 2; mt++)
#pragma unroll
        for (int hh = 0; hh < 2; hh++) {
            int m = wm * 32 + mt * 16 + g + hh * 8;
            if (m < rows) {
                tok_h[mt][hh] = d_slot_token[r0 + m];
                gat_h[mt][hh] = d_slot_gate[r0 + m];
            } else {
                tok_h[mt][hh] = -1;
                gat_h[mt][hh] = 0.f;
            }
        }

#pragma unroll
    for (int mt = 0; mt < 2; mt++) {
#pragma unroll
        for (int nt = 0; nt < 4; nt++) {
#pragma unroll
            for (int i = 0; i < 4; i++) {
                int hh = (i >= 2) ? 1 : 0;
                int tok = tok_h[mt][hh];
                if (tok >= 0) {
                    int n = n0 + wn * 32 + nt * 8 + tg * 2 + (i & 1);
                    atomicAdd(&out[(size_t)tok * H_DIM + n],
                              gat_h[mt][hh] * acc[mt][nt][i]);
                }
            }
        }
    }
}

// ---------------- launch ----------------
extern "C" void kernel_launch(void* const* d_in, const int* in_sizes, int n_in,
                              void* d_out, int out_size) {
    const float* hs     = (const float*)d_in[0];   // [T, H]
    const float* logits = (const float*)d_in[1];   // [T, E]
    const float* w1     = (const float*)d_in[2];   // [E, I, H]
    const float* w3     = (const float*)d_in[3];   // [E, I, H]
    const float* w2     = (const float*)d_in[4];   // [E, H, I]
    float* out = (float*)d_out;                    // [T, H]

    zero_kernel<<<(T_TOK * H_DIM) / 256, 256>>>(out);
    router_kernel<<<1, T_TOK>>>(logits);
    gemm1_kernel<<<dim3(I_DIM / BN, MAX_TILES), 256>>>(hs, w1, w3);
    gemm2_kernel<<<dim3(H_DIM / BN, MAX_TILES), 256>>>(w2, out);
}

// round 6
// speedup vs baseline: 1.4954x; 1.0026x over previous
#include <cuda_runtime.h>
#include <cuda_fp16.h>
#include <cstdint>
#include <math.h>

// Problem constants (fixed by the reference setup_inputs)
#define T_TOK   1024
#define H_DIM   1024
#define I_DIM   2816
#define E_NUM   8
#define S_NUM   (T_TOK * 2)      // 2048 (token, expert) slots
#define MAX_TILES 24

// GEMM tiling
#define BM 128
#define BN 64
#define BK 32
#define LDA 40                   // 32 + 8 halfs pad: 80B row stride -> conflict-free LDSM

// ---------------- device scratch (static, allocation-free) ----------------
__device__ int   d_slot_token[S_NUM];
__device__ float d_slot_gate[S_NUM];
__device__ int   d_tile_e[MAX_TILES];
__device__ int   d_tile_r0[MAX_TILES];
__device__ int   d_tile_r1[MAX_TILES];
__device__ int   d_num_tiles;
__device__ __align__(16) __half d_act[(size_t)S_NUM * I_DIM];   // 11.5 MB fp16

// ---------------- helpers ----------------
__device__ __forceinline__ uint32_t smem_u32(const void* p) {
    return (uint32_t)__cvta_generic_to_shared(p);
}

__device__ __forceinline__ void ldsm_x4(uint32_t* r, uint32_t addr) {
    asm volatile("ldmatrix.sync.aligned.m8n8.x4.shared.b16 {%0,%1,%2,%3}, [%4];"
                 : "=r"(r[0]), "=r"(r[1]), "=r"(r[2]), "=r"(r[3]) : "r"(addr));
}

__device__ __forceinline__ void mma_f16(float c[4], const uint32_t a[4], uint32_t b0, uint32_t b1) {
    asm volatile(
        "mma.sync.aligned.m16n8k16.row.col.f32.f16.f16.f32 "
        "{%0,%1,%2,%3}, {%4,%5,%6,%7}, {%8,%9}, {%0,%1,%2,%3};\n"
        : "+f"(c[0]), "+f"(c[1]), "+f"(c[2]), "+f"(c[3])
        : "r"(a[0]), "r"(a[1]), "r"(a[2]), "r"(a[3]), "r"(b0), "r"(b1));
}

__device__ __forceinline__ uint32_t pack2(float x, float y) {
    __half2 h = __floats2half2_rn(x, y);
    return *reinterpret_cast<uint32_t*>(&h);
}

// ---------------- zero output ----------------
__global__ void zero_kernel(float* __restrict__ out) {
    out[blockIdx.x * blockDim.x + threadIdx.x] = 0.0f;
}

// ---------------- router: top-2 softmax gates + expert-grouped slots ----------------
__global__ void router_kernel(const float* __restrict__ logits) {
    __shared__ int s_cnt[E_NUM];
    __shared__ int s_off[E_NUM + 1];
    __shared__ int s_cur[E_NUM];

    int t = threadIdx.x;            // one token per thread, blockDim == T_TOK
    if (t < E_NUM) s_cnt[t] = 0;
    __syncthreads();

    float l[E_NUM];
#pragma unroll
    for (int e = 0; e < E_NUM; e++) l[e] = logits[t * E_NUM + e];

    int e0 = 0;
#pragma unroll
    for (int e = 1; e < E_NUM; e++) if (l[e] > l[e0]) e0 = e;
    int e1 = (e0 == 0) ? 1 : 0;
#pragma unroll
    for (int e = 0; e < E_NUM; e++) if (e != e0 && l[e] > l[e1]) e1 = e;

    // renormalized top-2 softmax == softmax over {l0, l1}
    float d  = expf(l[e1] - l[e0]);       // <= 1
    float g0 = 1.0f / (1.0f + d);
    float g1 = 1.0f - g0;

    atomicAdd(&s_cnt[e0], 1);
    atomicAdd(&s_cnt[e1], 1);
    __syncthreads();

    if (t == 0) {
        int acc = 0;
        for (int e = 0; e < E_NUM; e++) { s_off[e] = acc; s_cur[e] = acc; acc += s_cnt[e]; }
        s_off[E_NUM] = acc;   // == S_NUM
    }
    __syncthreads();

    int p0 = atomicAdd(&s_cur[e0], 1);
    d_slot_token[p0] = t; d_slot_gate[p0] = g0;
    int p1 = atomicAdd(&s_cur[e1], 1);
    d_slot_token[p1] = t; d_slot_gate[p1] = g1;

    if (t == 0) {
        int nt = 0;
        for (int e = 0; e < E_NUM; e++) {
            for (int r = s_off[e]; r < s_off[e + 1]; r += BM) {
                d_tile_e[nt]  = e;
                d_tile_r0[nt] = r;
                d_tile_r1[nt] = min(r + BM, s_off[e + 1]);
                nt++;
            }
        }
        d_num_tiles = nt;
    }
}

// ---------------- GEMM1: act[slot, I] = silu(X@W1^T) * (X@W3^T), fp16 MMA ----------------
// grid: (I_DIM/BN, MAX_TILES), block: 256 (8 warps: 4 x 2)
__global__ __launch_bounds__(256, 1)
void gemm1_kernel(const float* __restrict__ X,
                  const float* __restrict__ W1,
                  const float* __restrict__ W3) {
    int tile = blockIdx.y;
    if (tile >= d_num_tiles) return;
    const int e    = d_tile_e[tile];
    const int r0   = d_tile_r0[tile];
    const int rows = d_tile_r1[tile] - r0;
    const int n0   = blockIdx.x * BN;

    __shared__ __half sA [BM * LDA];
    __shared__ __half sB1[BN * LDA];
    __shared__ __half sB3[BN * LDA];

    const int tid  = threadIdx.x;
    const int warp = tid >> 5, lane = tid & 31;
    const int g = lane >> 2, tg = lane & 3;
    const int wm = warp & 3, wn = warp >> 2;     // warp tile (wm*32, wn*32)
    const int lrow = tid >> 3;                   // 0..31
    const int lk   = (tid & 7) * 4;              // 0..28 step 4
    const int q = lane >> 3, j = lane & 7;       // ldmatrix lane decomposition

    int tok[4];
#pragma unroll
    for (int i = 0; i < 4; i++) {
        int r = lrow + 32 * i;
        tok[i] = (r < rows) ? d_slot_token[r0 + r] : -1;
    }

    const float* W1e = W1 + (size_t)e * I_DIM * H_DIM;
    const float* W3e = W3 + (size_t)e * I_DIM * H_DIM;

    // register staging (double buffer vs smem)
    float4 rA[4], rB1[2], rB3[2];
#pragma unroll
    for (int i = 0; i < 4; i++)
        rA[i] = (tok[i] >= 0) ? *(const float4*)(X + (size_t)tok[i] * H_DIM + lk)
                              : make_float4(0.f, 0.f, 0.f, 0.f);
#pragma unroll
    for (int i = 0; i < 2; i++) {
        rB1[i] = *(const float4*)(W1e + (size_t)(n0 + lrow + 32 * i) * H_DIM + lk);
        rB3[i] = *(const float4*)(W3e + (size_t)(n0 + lrow + 32 * i) * H_DIM + lk);
    }

    float acc1[2][4][4], acc3[2][4][4];
#pragma unroll
    for (int a = 0; a < 2; a++)
#pragma unroll
        for (int b = 0; b < 4; b++)
#pragma unroll
            for (int c = 0; c < 4; c++) { acc1[a][b][c] = 0.f; acc3[a][b][c] = 0.f; }

    for (int kt = 0; kt < H_DIM; kt += BK) {
        // commit staged regs to smem (fp32 -> fp16)
#pragma unroll
        for (int i = 0; i < 4; i++) {
            uint2 u;
            u.x = pack2(rA[i].x, rA[i].y);
            u.y = pack2(rA[i].z, rA[i].w);
            *(uint2*)&sA[(lrow + 32 * i) * LDA + lk] = u;
        }
#pragma unroll
        for (int i = 0; i < 2; i++) {
            uint2 u1, u3;
            u1.x = pack2(rB1[i].x, rB1[i].y); u1.y = pack2(rB1[i].z, rB1[i].w);
            u3.x = pack2(rB3[i].x, rB3[i].y); u3.y = pack2(rB3[i].z, rB3[i].w);
            *(uint2*)&sB1[(lrow + 32 * i) * LDA + lk] = u1;
            *(uint2*)&sB3[(lrow + 32 * i) * LDA + lk] = u3;
        }
        __syncthreads();

        // prefetch next K tile into registers
        if (kt + BK < H_DIM) {
            int kn = kt + BK;
#pragma unroll
            for (int i = 0; i < 4; i++)
                rA[i] = (tok[i] >= 0) ? *(const float4*)(X + (size_t)tok[i] * H_DIM + kn + lk)
                                      : make_float4(0.f, 0.f, 0.f, 0.f);
#pragma unroll
            for (int i = 0; i < 2; i++) {
                rB1[i] = *(const float4*)(W1e + (size_t)(n0 + lrow + 32 * i) * H_DIM + kn + lk);
                rB3[i] = *(const float4*)(W3e + (size_t)(n0 + lrow + 32 * i) * H_DIM + kn + lk);
            }
        }

        // compute: 2 k-steps of m16n8k16
#pragma unroll
        for (int ks = 0; ks < BK; ks += 16) {
            uint32_t af[2][4];
#pragma unroll
            for (int mt = 0; mt < 2; mt++) {
                int arow = wm * 32 + mt * 16 + j + (q & 1) * 8;
                int acol = ks + (q >> 1) * 8;
                ldsm_x4(af[mt], smem_u32(&sA[arow * LDA + acol]));
            }
            uint32_t bf1[2][4], bf3[2][4];
#pragma unroll
            for (int pr = 0; pr < 2; pr++) {
                int brow = wn * 32 + pr * 16 + j + (q >> 1) * 8;
                int bcol = ks + (q & 1) * 8;
                uint32_t addr1 = smem_u32(&sB1[brow * LDA + bcol]);
                uint32_t addr3 = smem_u32(&sB3[brow * LDA + bcol]);
                ldsm_x4(bf1[pr], addr1);
                ldsm_x4(bf3[pr], addr3);
            }
#pragma unroll
            for (int mt = 0; mt < 2; mt++)
#pragma unroll
                for (int nt = 0; nt < 4; nt++) {
                    int pr = nt >> 1, o = (nt & 1) * 2;
                    mma_f16(acc1[mt][nt], af[mt], bf1[pr][o], bf1[pr][o + 1]);
                    mma_f16(acc3[mt][nt], af[mt], bf3[pr][o], bf3[pr][o + 1]);
                }
        }
        __syncthreads();
    }

    // epilogue: act = silu(h1) * h3, stored fp16 as half2
#pragma unroll
    for (int mt = 0; mt < 2; mt++) {
#pragma unroll
        for (int nt = 0; nt < 4; nt++) {
#pragma unroll
            for (int p = 0; p < 2; p++) {
                int m = wm * 32 + mt * 16 + g + p * 8;
                if (m < rows) {
                    float h1a = acc1[mt][nt][2 * p],     h3a = acc3[mt][nt][2 * p];
                    float h1b = acc1[mt][nt][2 * p + 1], h3b = acc3[mt][nt][2 * p + 1];
                    float va = (h1a / (1.0f + __expf(-h1a))) * h3a;
                    float vb = (h1b / (1.0f + __expf(-h1b))) * h3b;
                    int n = n0 + wn * 32 + nt * 8 + tg * 2;
                    *(__half2*)&d_act[(size_t)(r0 + m) * I_DIM + n] =
                        __floats2half2_rn(va, vb);
                }
            }
        }
    }
}

// ---------------- GEMM2: out[token, H] += gate * (act @ W2^T), fp16 MMA ----------------
// grid: (H_DIM/BN, MAX_TILES), block: 256
__global__ __launch_bounds__(256, 1)
void gemm2_kernel(const float* __restrict__ W2, float* __restrict__ out) {
    int tile = blockIdx.y;
    if (tile >= d_num_tiles) return;
    const int e    = d_tile_e[tile];
    const int r0   = d_tile_r0[tile];
    const int rows = d_tile_r1[tile] - r0;
    const int n0   = blockIdx.x * BN;

    __shared__ __half sA[BM * LDA];
    __shared__ __half sB[BN * LDA];

    const int tid  = threadIdx.x;
    const int warp = tid >> 5, lane = tid & 31;
    const int g = lane >> 2, tg = lane & 3;
    const int wm = warp & 3, wn = warp >> 2;
    const int lrow = tid >> 3;
    const int lk   = (tid & 7) * 4;
    const int q = lane >> 3, j = lane & 7;

    const float* W2e = W2 + (size_t)e * H_DIM * I_DIM;

    bool arow_ok[4];
#pragma unroll
    for (int i = 0; i < 4; i++) arow_ok[i] = (lrow + 32 * i) < rows;

    uint2  rA[4];         // fp16 source: 4 halfs per load
    float4 rB[2];
#pragma unroll
    for (int i = 0; i < 4; i++)
        rA[i] = arow_ok[i] ? *(const uint2*)(d_act + (size_t)(r0 + lrow + 32 * i) * I_DIM + lk)
                           : make_uint2(0u, 0u);
#pragma unroll
    for (int i = 0; i < 2; i++)
        rB[i] = *(const float4*)(W2e + (size_t)(n0 + lrow + 32 * i) * I_DIM + lk);

    float acc[2][4][4];
#pragma unroll
    for (int a = 0; a < 2; a++)
#pragma unroll
        for (int b = 0; b < 4; b++)
#pragma unroll
            for (int c = 0; c < 4; c++) acc[a][b][c] = 0.f;

    for (int kt = 0; kt < I_DIM; kt += BK) {
#pragma unroll
        for (int i = 0; i < 4; i++)
            *(uint2*)&sA[(lrow + 32 * i) * LDA + lk] = rA[i];
#pragma unroll
        for (int i = 0; i < 2; i++) {
            uint2 u;
            u.x = pack2(rB[i].x, rB[i].y);
            u.y = pack2(rB[i].z, rB[i].w);
            *(uint2*)&sB[(lrow + 32 * i) * LDA + lk] = u;
        }
        __syncthreads();

        if (kt + BK < I_DIM) {
            int kn = kt + BK;
#pragma unroll
            for (int i = 0; i < 4; i++)
                rA[i] = arow_ok[i]
                      ? *(const uint2*)(d_act + (size_t)(r0 + lrow + 32 * i) * I_DIM + kn + lk)
                      : make_uint2(0u, 0u);
#pragma unroll
            for (int i = 0; i < 2; i++)
                rB[i] = *(const float4*)(W2e + (size_t)(n0 + lrow + 32 * i) * I_DIM + kn + lk);
        }

#pragma unroll
        for (int ks = 0; ks < BK; ks += 16) {
            uint32_t af[2][4];
#pragma unroll
            for (int mt = 0; mt < 2; mt++) {
                int arow = wm * 32 + mt * 16 + j + (q & 1) * 8;
                int acol = ks + (q >> 1) * 8;
                ldsm_x4(af[mt], smem_u32(&sA[arow * LDA + acol]));
            }
            uint32_t bf[2][4];
#pragma unroll
            for (int pr = 0; pr < 2; pr++) {
                int brow = wn * 32 + pr * 16 + j + (q >> 1) * 8;
                int bcol = ks + (q & 1) * 8;
                ldsm_x4(bf[pr], smem_u32(&sB[brow * LDA + bcol]));
            }
#pragma unroll
            for (int mt = 0; mt < 2; mt++)
#pragma unroll
                for (int nt = 0; nt < 4; nt++) {
                    int pr = nt >> 1, o = (nt & 1) * 2;
                    mma_f16(acc[mt][nt], af[mt], bf[pr][o], bf[pr][o + 1]);
                }
        }
        __syncthreads();
    }

    // epilogue: weighted scatter-add (exactly 2 contributions per (token, h);
    // fp32 add is commutative -> bitwise deterministic)
    int   tok_h[2][2];
    float gat_h[2][2];
#pragma unroll
    for (int mt = 0; mt < 2; mt++)
#pragma unroll
        for (int hh = 0; hh < 2; hh++) {
            int m = wm * 32 + mt * 16 + g + hh * 8;
            if (m < rows) {
                tok_h[mt][hh] = d_slot_token[r0 + m];
                gat_h[mt][hh] = d_slot_gate[r0 + m];
            } else {
                tok_h[mt][hh] = -1;
                gat_h[mt][hh] = 0.f;
            }
        }

#pragma unroll
    for (int mt = 0; mt < 2; mt++) {
#pragma unroll
        for (int nt = 0; nt < 4; nt++) {
#pragma unroll
            for (int i = 0; i < 4; i++) {
                int hh = (i >= 2) ? 1 : 0;
                int tok = tok_h[mt][hh];
                if (tok >= 0) {
                    int n = n0 + wn * 32 + nt * 8 + tg * 2 + (i & 1);
                    atomicAdd(&out[(size_t)tok * H_DIM + n],
                              gat_h[mt][hh] * acc[mt][nt][i]);
                }
            }
        }
    }
}

// ---------------- launch ----------------
extern "C" void kernel_launch(void* const* d_in, const int* in_sizes, int n_in,
                              void* d_out, int out_size) {
    const float* hs     = (const float*)d_in[0];   // [T, H]
    const float* logits = (const float*)d_in[1];   // [T, E]
    const float* w1     = (const float*)d_in[2];   // [E, I, H]
    const float* w3     = (const float*)d_in[3];   // [E, I, H]
    const float* w2     = (const float*)d_in[4];   // [E, H, I]
    float* out = (float*)d_out;                    // [T, H]

    zero_kernel<<<(T_TOK * H_DIM) / 256, 256>>>(out);
    router_kernel<<<1, T_TOK>>>(logits);
    gemm1_kernel<<<dim3(I_DIM / BN, MAX_TILES), 256>>>(hs, w1, w3);
    gemm2_kernel<<<dim3(H_DIM / BN, MAX_TILES), 256>>>(w2, out);
}